// round 1
// baseline (speedup 1.0000x reference)
#include <cuda_runtime.h>

// Problem constants (fixed shapes per reference)
#define M_TOTAL 8192      // BATCH * SEQ
#define K_DIM   4096      // D_IN
#define N_DIM   4096      // D_OUT
#define LRANK   16

// Scratch for LoRA intermediate t = x @ A^T  : [M_TOTAL, LRANK]
__device__ float g_t[M_TOTAL * LRANK];

// ---------------------------------------------------------------------------
// Kernel 1: t[m][r] = sum_k x[m][k] * A[r][k]
// Block: 256 threads, covers 64 m-rows, tiles K by 64 through shared memory.
// ---------------------------------------------------------------------------
__global__ __launch_bounds__(256)
void lora_xa_kernel(const float* __restrict__ x, const float* __restrict__ A)
{
    __shared__ float xs[64][65];   // [m_local][k_local], padded
    __shared__ float as[16][65];   // [r][k_local], padded

    const int m0 = blockIdx.x * 64;
    const int r  = threadIdx.x % 16;   // compute role: which rank row
    const int mq = threadIdx.x / 16;   // compute role: which 4-row group

    // loader roles
    const int lrow = threadIdx.x / 16;        // 0..15
    const int lc4  = (threadIdx.x % 16) * 4;  // 0..60

    float acc[4] = {0.f, 0.f, 0.f, 0.f};

    for (int k0 = 0; k0 < K_DIM; k0 += 64) {
        // load x tile: 64 rows x 64 cols
        #pragma unroll
        for (int i = 0; i < 4; i++) {
            float4 v = *(const float4*)&x[(size_t)(m0 + lrow + 16 * i) * K_DIM + k0 + lc4];
            xs[lrow + 16 * i][lc4 + 0] = v.x;
            xs[lrow + 16 * i][lc4 + 1] = v.y;
            xs[lrow + 16 * i][lc4 + 2] = v.z;
            xs[lrow + 16 * i][lc4 + 3] = v.w;
        }
        // load A tile: 16 rows x 64 cols (one float4 per thread)
        {
            float4 v = *(const float4*)&A[(size_t)lrow * K_DIM + k0 + lc4];
            as[lrow][lc4 + 0] = v.x;
            as[lrow][lc4 + 1] = v.y;
            as[lrow][lc4 + 2] = v.z;
            as[lrow][lc4 + 3] = v.w;
        }
        __syncthreads();

        #pragma unroll 8
        for (int k = 0; k < 64; k++) {
            float a = as[r][k];
            #pragma unroll
            for (int i = 0; i < 4; i++)
                acc[i] += xs[mq * 4 + i][k] * a;
        }
        __syncthreads();
    }

    #pragma unroll
    for (int i = 0; i < 4; i++)
        g_t[(size_t)(m0 + mq * 4 + i) * LRANK + r] = acc[i];
}

// ---------------------------------------------------------------------------
// Kernel 2: out[m][n] = sum_k x[m][k]*W[n][k] + bias[n] + sum_r t[m][r]*B[n][r]
// Classic 128x128x8 SGEMM, 8x8 per thread, 256 threads, fused LoRA epilogue.
// ---------------------------------------------------------------------------
__global__ __launch_bounds__(256, 2)
void sgemm_lora_kernel(const float* __restrict__ x,
                       const float* __restrict__ W,
                       const float* __restrict__ bias,
                       const float* __restrict__ Bmat,
                       const float* __restrict__ t,
                       float* __restrict__ out)
{
    __shared__ float As[8][128];      // [k][m]
    __shared__ float Bs[8][128];      // [k][n]
    __shared__ float Ts[128 * 16];    // t tile, row-major [m_local][r]
    __shared__ float Bls[16 * 128];   // B tile transposed [r][n_local]

    const int m0 = blockIdx.y * 128;
    const int n0 = blockIdx.x * 128;

    const int tx = threadIdx.x % 16;  // n direction
    const int ty = threadIdx.x / 16;  // m direction

    // loader roles: 256 threads load 128x8 tiles (one float4 each)
    const int lrow = threadIdx.x / 2;         // 0..127
    const int lcol = (threadIdx.x % 2) * 4;   // 0 or 4

    float acc[8][8];
    #pragma unroll
    for (int i = 0; i < 8; i++)
        #pragma unroll
        for (int j = 0; j < 8; j++)
            acc[i][j] = 0.f;

    const float* xg = &x[(size_t)(m0 + lrow) * K_DIM + lcol];
    const float* wg = &W[(size_t)(n0 + lrow) * K_DIM + lcol];

    for (int k0 = 0; k0 < K_DIM; k0 += 8) {
        float4 av = *(const float4*)(xg + k0);
        float4 bv = *(const float4*)(wg + k0);

        __syncthreads();   // previous iteration's reads complete before overwrite

        As[lcol + 0][lrow] = av.x;
        As[lcol + 1][lrow] = av.y;
        As[lcol + 2][lrow] = av.z;
        As[lcol + 3][lrow] = av.w;
        Bs[lcol + 0][lrow] = bv.x;
        Bs[lcol + 1][lrow] = bv.y;
        Bs[lcol + 2][lrow] = bv.z;
        Bs[lcol + 3][lrow] = bv.w;

        __syncthreads();

        #pragma unroll
        for (int k = 0; k < 8; k++) {
            float a[8], b[8];
            *(float4*)&a[0] = *(const float4*)&As[k][ty * 8];
            *(float4*)&a[4] = *(const float4*)&As[k][ty * 8 + 4];
            *(float4*)&b[0] = *(const float4*)&Bs[k][tx * 8];
            *(float4*)&b[4] = *(const float4*)&Bs[k][tx * 8 + 4];
            #pragma unroll
            for (int i = 0; i < 8; i++)
                #pragma unroll
                for (int j = 0; j < 8; j++)
                    acc[i][j] += a[i] * b[j];
        }
    }

    // ---- Epilogue staging: t tile and B tile ----
    {
        // t: rows m0..m0+127, 16 each -> 2048 contiguous floats
        const float4* tg = (const float4*)(t + (size_t)m0 * LRANK);
        float4* ts4 = (float4*)Ts;
        ts4[threadIdx.x]       = tg[threadIdx.x];
        ts4[threadIdx.x + 256] = tg[threadIdx.x + 256];

        // B: [n][r] -> transposed into Bls[r][n_local]
        int nl = threadIdx.x / 2;
        int r0 = (threadIdx.x % 2) * 8;
        float4 b0 = *(const float4*)&Bmat[(size_t)(n0 + nl) * LRANK + r0];
        float4 b1 = *(const float4*)&Bmat[(size_t)(n0 + nl) * LRANK + r0 + 4];
        Bls[(r0 + 0) * 128 + nl] = b0.x;
        Bls[(r0 + 1) * 128 + nl] = b0.y;
        Bls[(r0 + 2) * 128 + nl] = b0.z;
        Bls[(r0 + 3) * 128 + nl] = b0.w;
        Bls[(r0 + 4) * 128 + nl] = b1.x;
        Bls[(r0 + 5) * 128 + nl] = b1.y;
        Bls[(r0 + 6) * 128 + nl] = b1.z;
        Bls[(r0 + 7) * 128 + nl] = b1.w;
    }
    __syncthreads();

    // LoRA rank-16 contribution
    #pragma unroll
    for (int r = 0; r < 16; r++) {
        float av[8], bv[8];
        #pragma unroll
        for (int i = 0; i < 8; i++)
            av[i] = Ts[(ty * 8 + i) * 16 + r];
        *(float4*)&bv[0] = *(const float4*)&Bls[r * 128 + tx * 8];
        *(float4*)&bv[4] = *(const float4*)&Bls[r * 128 + tx * 8 + 4];
        #pragma unroll
        for (int i = 0; i < 8; i++)
            #pragma unroll
            for (int j = 0; j < 8; j++)
                acc[i][j] += av[i] * bv[j];
    }

    // bias + store
    float bb[8];
    *(float4*)&bb[0] = *(const float4*)&bias[n0 + tx * 8];
    *(float4*)&bb[4] = *(const float4*)&bias[n0 + tx * 8 + 4];

    #pragma unroll
    for (int i = 0; i < 8; i++) {
        size_t row = (size_t)(m0 + ty * 8 + i);
        float4 o0, o1;
        o0.x = acc[i][0] + bb[0];
        o0.y = acc[i][1] + bb[1];
        o0.z = acc[i][2] + bb[2];
        o0.w = acc[i][3] + bb[3];
        o1.x = acc[i][4] + bb[4];
        o1.y = acc[i][5] + bb[5];
        o1.z = acc[i][6] + bb[6];
        o1.w = acc[i][7] + bb[7];
        *(float4*)&out[row * N_DIM + n0 + tx * 8]     = o0;
        *(float4*)&out[row * N_DIM + n0 + tx * 8 + 4] = o1;
    }
}

// ---------------------------------------------------------------------------
extern "C" void kernel_launch(void* const* d_in, const int* in_sizes, int n_in,
                              void* d_out, int out_size)
{
    (void)in_sizes; (void)n_in; (void)out_size;
    const float* x    = (const float*)d_in[0];  // [2,4096,4096]
    const float* W    = (const float*)d_in[1];  // [4096,4096]
    const float* bias = (const float*)d_in[2];  // [4096]
    const float* A    = (const float*)d_in[3];  // [16,4096]
    const float* Bm   = (const float*)d_in[4];  // [4096,16]
    float* out        = (float*)d_out;          // [2,4096,4096]

    float* t = nullptr;
    cudaGetSymbolAddress((void**)&t, g_t);

    // Kernel 1: t = x @ A^T
    lora_xa_kernel<<<M_TOTAL / 64, 256>>>(x, A);

    // Kernel 2: fused SGEMM + bias + LoRA epilogue
    dim3 grid(N_DIM / 128, M_TOTAL / 128);
    sgemm_lora_kernel<<<grid, 256>>>(x, W, bias, Bm, t, out);
}

// round 3
// speedup vs baseline: 3.6901x; 3.6901x over previous
#include <cuda_runtime.h>
#include <cuda_bf16.h>
#include <cstdint>

// ---------------- problem constants ----------------
#define M_TOTAL 8192
#define K_DIM   4096
#define N_DIM   4096
#define LRANK   16

#define TM 128
#define TN 128
#define KC 64                     // bf16 elems per k-chunk (128B rows, SW128)
#define NCHUNK (K_DIM / KC)       // 64
#define MT (M_TOTAL / TM)         // 64
#define NT (N_DIM / TN)           // 32

#define A_BLK 32768               // 128x64 bf16 hi(16KB)+lo(16KB)
#define W_BLK 32768               // 128x64 bf16 hi+lo
#define STAGE_BYTES 65536         // A_BLK + W_BLK
#define SMEM_TOTAL (2 * STAGE_BYTES)

// pre-converted, pre-swizzled operands (device globals = sanctioned scratch)
__device__ __align__(1024) unsigned char g_x[(size_t)MT * NCHUNK * A_BLK]; // 128MB
__device__ __align__(1024) unsigned char g_w[(size_t)NT * NCHUNK * W_BLK]; //  64MB

static __device__ __forceinline__ uint32_t smem_u32(const void* p) {
    uint32_t a;
    asm("{ .reg .u64 t; cvta.to.shared.u64 t, %1; cvt.u32.u64 %0, t; }" : "=r"(a) : "l"(p));
    return a;
}

static __device__ __forceinline__ void cp16(uint32_t dst, const void* src) {
    asm volatile("cp.async.cg.shared.global [%0], [%1], 16;" :: "r"(dst), "l"(src) : "memory");
}

#define LDSM_X4(r0, r1, r2, r3, addr)                                          \
    asm volatile("ldmatrix.sync.aligned.m8n8.x4.shared.b16 {%0,%1,%2,%3}, [%4];" \
        : "=r"(r0), "=r"(r1), "=r"(r2), "=r"(r3) : "r"(addr))

#define MMA16816(d, a0, a1, a2, a3, b0, b1)                                    \
    asm volatile("mma.sync.aligned.m16n8k16.row.col.f32.bf16.bf16.f32 "        \
        "{%0,%1,%2,%3}, {%4,%5,%6,%7}, {%8,%9}, {%0,%1,%2,%3};"                \
        : "+f"((d)[0]), "+f"((d)[1]), "+f"((d)[2]), "+f"((d)[3])               \
        : "r"(a0), "r"(a1), "r"(a2), "r"(a3), "r"(b0), "r"(b1))

// ===========================================================================
// conv_x: x fp32 -> bf16 hi/lo, SW128-swizzled 128x64 blocks
// block index = mt*NCHUNK + kc ; [hi 16KB][lo 16KB]
// ===========================================================================
__global__ __launch_bounds__(256)
void conv_x_kernel(const float* __restrict__ x)
{
    const int kc = blockIdx.x, mt = blockIdx.y;
    const int k0 = kc * KC, m0 = mt * TM;
    unsigned char* blk = g_x + ((size_t)(mt * NCHUNK + kc) * A_BLK);
    const int t = threadIdx.x;
    #pragma unroll
    for (int i = 0; i < (TM * KC) / 256; i++) {
        int e = t + 256 * i;
        int r = e >> 6, c = e & 63;
        float v = x[(size_t)(m0 + r) * K_DIM + k0 + c];
        __nv_bfloat16 hi = __float2bfloat16(v);
        __nv_bfloat16 lo = __float2bfloat16(v - __bfloat162float(hi));
        uint32_t off = (uint32_t)r * 128 + (uint32_t)c * 2;
        uint32_t sw = off ^ ((off >> 3) & 0x70);
        *(__nv_bfloat16*)(blk + sw)         = hi;
        *(__nv_bfloat16*)(blk + 16384 + sw) = lo;
    }
}

// ===========================================================================
// conv_w: W' = W + B@A -> bf16 hi/lo, SW128-swizzled 128x64 blocks
// grid (NCHUNK, 64): each block does 64 n-rows x 64 k-cols
// ===========================================================================
__global__ __launch_bounds__(256)
void conv_w_kernel(const float* __restrict__ W, const float* __restrict__ Amat,
                   const float* __restrict__ Bmat)
{
    __shared__ float As[16][64];
    __shared__ float Bs[64][16];
    const int kc = blockIdx.x, by = blockIdx.y;
    const int k0 = kc * KC, n0 = by * 64;
    const int t = threadIdx.x;

    {   // A slab 16x64
        int r = t / 16, c4 = (t % 16) * 4;
        float4 v = *(const float4*)&Amat[(size_t)r * K_DIM + k0 + c4];
        As[r][c4+0] = v.x; As[r][c4+1] = v.y; As[r][c4+2] = v.z; As[r][c4+3] = v.w;
    }
    {   // B slab 64x16
        int nl = t / 4, r4 = (t % 4) * 4;
        float4 v = *(const float4*)&Bmat[(size_t)(n0 + nl) * LRANK + r4];
        Bs[nl][r4+0] = v.x; Bs[nl][r4+1] = v.y; Bs[nl][r4+2] = v.z; Bs[nl][r4+3] = v.w;
    }
    __syncthreads();

    const int n_tile = by >> 1;            // 128-row tiles
    const int row_base = (by & 1) * 64;
    unsigned char* blk = g_w + ((size_t)(n_tile * NCHUNK + kc) * W_BLK);

    #pragma unroll
    for (int i = 0; i < 16; i++) {
        int e = t + 256 * i;
        int rl = e >> 6, c = e & 63;
        float acc = W[(size_t)(n0 + rl) * K_DIM + k0 + c];
        #pragma unroll
        for (int r = 0; r < 16; r++) acc += Bs[rl][r] * As[r][c];
        __nv_bfloat16 hi = __float2bfloat16(acc);
        __nv_bfloat16 lo = __float2bfloat16(acc - __bfloat162float(hi));
        uint32_t off = (uint32_t)(row_base + rl) * 128 + (uint32_t)c * 2;
        uint32_t sw = off ^ ((off >> 3) & 0x70);
        *(__nv_bfloat16*)(blk + sw)         = hi;
        *(__nv_bfloat16*)(blk + 16384 + sw) = lo;
    }
}

// ===========================================================================
// GEMM: out = x @ W'^T + bias  via bf16 3-term split on HMMA (mma.sync)
// CTA 128x128, 8 warps (4x2), warp tile 32x64, double-buffered cp.async
// ===========================================================================
__global__ __launch_bounds__(256, 1)
void gemm_mma_kernel(const float* __restrict__ bias, float* __restrict__ out)
{
    extern __shared__ __align__(1024) unsigned char smem[];
    const uint32_t sbase = smem_u32(smem);
    const int tid  = threadIdx.x;
    const int lane = tid & 31;
    const int wid  = tid >> 5;
    const int wm   = wid & 3;          // 4 m-groups of 32
    const int wn   = wid >> 2;         // 2 n-groups of 64
    const int nt = blockIdx.x, mt = blockIdx.y;
    const int m0 = mt * TM, n0 = nt * TN;

    const unsigned char* ga = g_x + (size_t)(mt * NCHUNK) * A_BLK;
    const unsigned char* gb = g_w + (size_t)(nt * NCHUNK) * W_BLK;

    // ---- per-thread ldmatrix addressing (SW128) ----
    // A: matrices {rows0-7@k0, rows8-15@k0, rows0-7@k8, rows8-15@k8}
    const int aRow = wm * 32 + ((lane >> 3) & 1) * 8 + (lane & 7);
    const uint32_t aKsel = (lane >> 4) * 16;            // +16B for k+8 halves
    // B: matrices {n0-7@k0, n0-7@k8, n8-15@k0, n8-15@k8}
    const int bRow = wn * 64 + ((lane >> 4) & 1) * 8 + (lane & 7);
    const uint32_t bKsel = ((lane >> 3) & 1) * 16;
    const uint32_t X = (uint32_t)(lane & 7) << 4;       // swizzle XOR (row&7)<<4

    float acc[2][8][4];
    #pragma unroll
    for (int i = 0; i < 2; i++)
        #pragma unroll
        for (int j = 0; j < 8; j++)
            #pragma unroll
            for (int q = 0; q < 4; q++) acc[i][j][q] = 0.f;

    // ---- async copy of one chunk into stage s ----
    auto issue = [&](int c, int s) {
        const unsigned char* srcA = ga + (size_t)c * A_BLK;
        const unsigned char* srcB = gb + (size_t)c * W_BLK;
        uint32_t st = sbase + s * STAGE_BYTES;
        #pragma unroll
        for (int i = 0; i < 8; i++) {
            uint32_t off = (uint32_t)tid * 16 + i * 4096;
            cp16(st + off, srcA + off);
        }
        #pragma unroll
        for (int i = 0; i < 8; i++) {
            uint32_t off = (uint32_t)tid * 16 + i * 4096;
            cp16(st + 32768 + off, srcB + off);
        }
        asm volatile("cp.async.commit_group;" ::: "memory");
    };

    issue(0, 0);
    issue(1, 1);

    for (int c = 0; c < NCHUNK; c++) {
        const int s = c & 1;
        asm volatile("cp.async.wait_group 1;" ::: "memory");
        __syncthreads();

        const uint32_t Ahi = sbase + s * STAGE_BYTES;
        const uint32_t Alo = Ahi + 16384;
        const uint32_t Bhi = Ahi + 32768;
        const uint32_t Blo = Ahi + 49152;

        #pragma unroll
        for (int ks = 0; ks < 4; ks++) {
            const uint32_t kb = (uint32_t)ks * 32;           // k0*2 bytes
            const uint32_t aoff = (kb + aKsel) ^ X;
            const uint32_t boff = (kb + bKsel) ^ X;

            uint32_t aH[2][4], aL[2][4];
            #pragma unroll
            for (int m2 = 0; m2 < 2; m2++) {
                uint32_t rb = (uint32_t)(aRow + 16 * m2) * 128;
                LDSM_X4(aH[m2][0], aH[m2][1], aH[m2][2], aH[m2][3], Ahi + rb + aoff);
                LDSM_X4(aL[m2][0], aL[m2][1], aL[m2][2], aL[m2][3], Alo + rb + aoff);
            }
            uint32_t bH[4][4], bL[4][4];
            #pragma unroll
            for (int n4 = 0; n4 < 4; n4++) {
                uint32_t rb = (uint32_t)(bRow + 16 * n4) * 128;
                LDSM_X4(bH[n4][0], bH[n4][1], bH[n4][2], bH[n4][3], Bhi + rb + boff);
                LDSM_X4(bL[n4][0], bL[n4][1], bL[n4][2], bL[n4][3], Blo + rb + boff);
            }

            #pragma unroll
            for (int m2 = 0; m2 < 2; m2++) {
                #pragma unroll
                for (int nj = 0; nj < 8; nj++) {
                    const int g = nj >> 1, h = (nj & 1) * 2;
                    MMA16816(acc[m2][nj], aH[m2][0], aH[m2][1], aH[m2][2], aH[m2][3],
                             bH[g][h], bH[g][h + 1]);
                    MMA16816(acc[m2][nj], aH[m2][0], aH[m2][1], aH[m2][2], aH[m2][3],
                             bL[g][h], bL[g][h + 1]);
                    MMA16816(acc[m2][nj], aL[m2][0], aL[m2][1], aL[m2][2], aL[m2][3],
                             bH[g][h], bH[g][h + 1]);
                }
            }
        }

        __syncthreads();
        if (c + 2 < NCHUNK) issue(c + 2, s);
    }

    // ---- epilogue: bias + store ----
    const int rrow = m0 + wm * 32 + (lane >> 2);
    const int ncol = n0 + wn * 64 + (lane & 3) * 2;

    float2 bb[8];
    #pragma unroll
    for (int nj = 0; nj < 8; nj++)
        bb[nj] = *(const float2*)&bias[ncol + nj * 8];

    #pragma unroll
    for (int m2 = 0; m2 < 2; m2++) {
        #pragma unroll
        for (int nj = 0; nj < 8; nj++) {
            const int n = ncol + nj * 8;
            size_t r0 = (size_t)(rrow + m2 * 16) * N_DIM + n;
            size_t r1 = r0 + 8 * N_DIM;
            float2 o0, o1;
            o0.x = acc[m2][nj][0] + bb[nj].x;
            o0.y = acc[m2][nj][1] + bb[nj].y;
            o1.x = acc[m2][nj][2] + bb[nj].x;
            o1.y = acc[m2][nj][3] + bb[nj].y;
            *(float2*)&out[r0] = o0;
            *(float2*)&out[r1] = o1;
        }
    }
}

// ===========================================================================
extern "C" void kernel_launch(void* const* d_in, const int* in_sizes, int n_in,
                              void* d_out, int out_size)
{
    (void)in_sizes; (void)n_in; (void)out_size;
    const float* x    = (const float*)d_in[0];
    const float* W    = (const float*)d_in[1];
    const float* bias = (const float*)d_in[2];
    const float* A    = (const float*)d_in[3];
    const float* Bm   = (const float*)d_in[4];
    float* out        = (float*)d_out;

    cudaFuncSetAttribute(gemm_mma_kernel,
                         cudaFuncAttributeMaxDynamicSharedMemorySize, SMEM_TOTAL);

    conv_x_kernel<<<dim3(NCHUNK, MT), 256>>>(x);
    conv_w_kernel<<<dim3(NCHUNK, 64), 256>>>(W, A, Bm);
    gemm_mma_kernel<<<dim3(NT, MT), 256, SMEM_TOTAL>>>(bias, out);
}

// round 4
// speedup vs baseline: 5.1810x; 1.4040x over previous
#include <cuda_runtime.h>
#include <cuda_fp16.h>
#include <cstdint>

// ---------------- problem constants ----------------
#define M_TOTAL 8192
#define K_DIM   4096
#define N_DIM   4096
#define LRANK   16

#define TM 128
#define TN 128
#define KC 64                     // fp16 elems per k-chunk (128B rows, SW128)
#define NCHUNK (K_DIM / KC)       // 64
#define MT (M_TOTAL / TM)         // 64
#define NT (N_DIM / TN)           // 32

#define A_BLK 16384               // 128x64 fp16 hi only
#define W_BLK 32768               // 128x64 fp16 hi(16KB)+lo(16KB)
#define STAGE_BYTES 49152         // A_BLK + W_BLK
#define NSTAGE 3
#define SMEM_TOTAL (NSTAGE * STAGE_BYTES)   // 147456

// pre-converted, pre-swizzled operands (device globals = sanctioned scratch)
__device__ __align__(1024) unsigned char g_x[(size_t)MT * NCHUNK * A_BLK]; // 64MB
__device__ __align__(1024) unsigned char g_w[(size_t)NT * NCHUNK * W_BLK]; // 64MB

static __device__ __forceinline__ uint32_t smem_u32(const void* p) {
    uint32_t a;
    asm("{ .reg .u64 t; cvta.to.shared.u64 t, %1; cvt.u32.u64 %0, t; }" : "=r"(a) : "l"(p));
    return a;
}

static __device__ __forceinline__ void cp16(uint32_t dst, const void* src) {
    asm volatile("cp.async.cg.shared.global [%0], [%1], 16;" :: "r"(dst), "l"(src) : "memory");
}

#define LDSM_X4(r0, r1, r2, r3, addr)                                          \
    asm volatile("ldmatrix.sync.aligned.m8n8.x4.shared.b16 {%0,%1,%2,%3}, [%4];" \
        : "=r"(r0), "=r"(r1), "=r"(r2), "=r"(r3) : "r"(addr))

#define MMA16816(d, a0, a1, a2, a3, b0, b1)                                    \
    asm volatile("mma.sync.aligned.m16n8k16.row.col.f32.f16.f16.f32 "          \
        "{%0,%1,%2,%3}, {%4,%5,%6,%7}, {%8,%9}, {%0,%1,%2,%3};"                \
        : "+f"((d)[0]), "+f"((d)[1]), "+f"((d)[2]), "+f"((d)[3])               \
        : "r"(a0), "r"(a1), "r"(a2), "r"(a3), "r"(b0), "r"(b1))

// ===========================================================================
// conv_x: x fp32 -> fp16 (single), SW128-swizzled 128x64 blocks
// ===========================================================================
__global__ __launch_bounds__(256)
void conv_x_kernel(const float* __restrict__ x)
{
    const int kc = blockIdx.x, mt = blockIdx.y;
    const int k0 = kc * KC, m0 = mt * TM;
    unsigned char* blk = g_x + ((size_t)(mt * NCHUNK + kc) * A_BLK);
    const int t = threadIdx.x;
    #pragma unroll
    for (int i = 0; i < (TM * KC) / 256; i++) {
        int e = t + 256 * i;
        int r = e >> 6, c = e & 63;
        float v = x[(size_t)(m0 + r) * K_DIM + k0 + c];
        uint32_t off = (uint32_t)r * 128 + (uint32_t)c * 2;
        uint32_t sw = off ^ ((off >> 3) & 0x70);
        *(__half*)(blk + sw) = __float2half_rn(v);
    }
}

// ===========================================================================
// conv_w: W' = W + B@A -> fp16 hi/lo, SW128-swizzled 128x64 blocks
// grid (NCHUNK, 64): each block does 64 n-rows x 64 k-cols
// ===========================================================================
__global__ __launch_bounds__(256)
void conv_w_kernel(const float* __restrict__ W, const float* __restrict__ Amat,
                   const float* __restrict__ Bmat)
{
    __shared__ float As[16][64];
    __shared__ float Bs[64][16];
    const int kc = blockIdx.x, by = blockIdx.y;
    const int k0 = kc * KC, n0 = by * 64;
    const int t = threadIdx.x;

    {   // A slab 16x64
        int r = t / 16, c4 = (t % 16) * 4;
        float4 v = *(const float4*)&Amat[(size_t)r * K_DIM + k0 + c4];
        As[r][c4+0] = v.x; As[r][c4+1] = v.y; As[r][c4+2] = v.z; As[r][c4+3] = v.w;
    }
    {   // B slab 64x16
        int nl = t / 4, r4 = (t % 4) * 4;
        float4 v = *(const float4*)&Bmat[(size_t)(n0 + nl) * LRANK + r4];
        Bs[nl][r4+0] = v.x; Bs[nl][r4+1] = v.y; Bs[nl][r4+2] = v.z; Bs[nl][r4+3] = v.w;
    }
    __syncthreads();

    const int n_tile = by >> 1;            // 128-row tiles
    const int row_base = (by & 1) * 64;
    unsigned char* blk = g_w + ((size_t)(n_tile * NCHUNK + kc) * W_BLK);

    #pragma unroll
    for (int i = 0; i < 16; i++) {
        int e = t + 256 * i;
        int rl = e >> 6, c = e & 63;
        float acc = W[(size_t)(n0 + rl) * K_DIM + k0 + c];
        #pragma unroll
        for (int r = 0; r < 16; r++) acc += Bs[rl][r] * As[r][c];
        __half hi = __float2half_rn(acc);
        __half lo = __float2half_rn(acc - __half2float(hi));
        uint32_t off = (uint32_t)(row_base + rl) * 128 + (uint32_t)c * 2;
        uint32_t sw = off ^ ((off >> 3) & 0x70);
        *(__half*)(blk + sw)         = hi;
        *(__half*)(blk + 16384 + sw) = lo;
    }
}

// ===========================================================================
// GEMM: out = x @ W'^T + bias  via fp16 2-term split on HMMA (mma.sync)
// CTA 128x128, 8 warps (4x2), warp tile 32x64, 3-stage cp.async pipeline
// ===========================================================================
__global__ __launch_bounds__(256, 1)
void gemm_mma_kernel(const float* __restrict__ bias, float* __restrict__ out)
{
    extern __shared__ __align__(1024) unsigned char smem[];
    const uint32_t sbase = smem_u32(smem);
    const int tid  = threadIdx.x;
    const int lane = tid & 31;
    const int wid  = tid >> 5;
    const int wm   = wid & 3;          // 4 m-groups of 32
    const int wn   = wid >> 2;         // 2 n-groups of 64
    const int nt = blockIdx.x, mt = blockIdx.y;
    const int m0 = mt * TM, n0 = nt * TN;

    const unsigned char* ga = g_x + (size_t)(mt * NCHUNK) * A_BLK;
    const unsigned char* gb = g_w + (size_t)(nt * NCHUNK) * W_BLK;

    // ---- per-thread ldmatrix addressing (SW128) ----
    const int aRow = wm * 32 + ((lane >> 3) & 1) * 8 + (lane & 7);
    const uint32_t aKsel = (lane >> 4) * 16;            // +16B for k+8 halves
    const int bRow = wn * 64 + ((lane >> 4) & 1) * 8 + (lane & 7);
    const uint32_t bKsel = ((lane >> 3) & 1) * 16;
    const uint32_t X = (uint32_t)(lane & 7) << 4;       // swizzle XOR (row&7)<<4

    float acc[2][8][4];
    #pragma unroll
    for (int i = 0; i < 2; i++)
        #pragma unroll
        for (int j = 0; j < 8; j++)
            #pragma unroll
            for (int q = 0; q < 4; q++) acc[i][j][q] = 0.f;

    // ---- async copy of one chunk into stage s ----
    auto issue = [&](int c, int s) {
        const unsigned char* srcA = ga + (size_t)c * A_BLK;
        const unsigned char* srcB = gb + (size_t)c * W_BLK;
        uint32_t st = sbase + s * STAGE_BYTES;
        #pragma unroll
        for (int i = 0; i < 4; i++) {
            uint32_t off = (uint32_t)tid * 16 + i * 4096;
            cp16(st + off, srcA + off);
        }
        #pragma unroll
        for (int i = 0; i < 8; i++) {
            uint32_t off = (uint32_t)tid * 16 + i * 4096;
            cp16(st + A_BLK + off, srcB + off);
        }
        asm volatile("cp.async.commit_group;" ::: "memory");
    };

    issue(0, 0);
    issue(1, 1);
    issue(2, 2);

    int s = 0;
    for (int c = 0; c < NCHUNK; c++) {
        asm volatile("cp.async.wait_group 2;" ::: "memory");
        __syncthreads();

        const uint32_t Ahi = sbase + s * STAGE_BYTES;
        const uint32_t Bhi = Ahi + A_BLK;
        const uint32_t Blo = Bhi + 16384;

        #pragma unroll
        for (int ks = 0; ks < 4; ks++) {
            const uint32_t kb = (uint32_t)ks * 32;           // k0*2 bytes
            const uint32_t aoff = (kb + aKsel) ^ X;
            const uint32_t boff = (kb + bKsel) ^ X;

            uint32_t aH[2][4];
            #pragma unroll
            for (int m2 = 0; m2 < 2; m2++) {
                uint32_t rb = (uint32_t)(aRow + 16 * m2) * 128;
                LDSM_X4(aH[m2][0], aH[m2][1], aH[m2][2], aH[m2][3], Ahi + rb + aoff);
            }
            uint32_t bH[4][4], bL[4][4];
            #pragma unroll
            for (int n4 = 0; n4 < 4; n4++) {
                uint32_t rb = (uint32_t)(bRow + 16 * n4) * 128;
                LDSM_X4(bH[n4][0], bH[n4][1], bH[n4][2], bH[n4][3], Bhi + rb + boff);
                LDSM_X4(bL[n4][0], bL[n4][1], bL[n4][2], bL[n4][3], Blo + rb + boff);
            }

            #pragma unroll
            for (int m2 = 0; m2 < 2; m2++) {
                #pragma unroll
                for (int nj = 0; nj < 8; nj++) {
                    const int g = nj >> 1, h = (nj & 1) * 2;
                    MMA16816(acc[m2][nj], aH[m2][0], aH[m2][1], aH[m2][2], aH[m2][3],
                             bH[g][h], bH[g][h + 1]);
                    MMA16816(acc[m2][nj], aH[m2][0], aH[m2][1], aH[m2][2], aH[m2][3],
                             bL[g][h], bL[g][h + 1]);
                }
            }
        }

        __syncthreads();
        if (c + 3 < NCHUNK) issue(c + 3, s);
        s = (s == NSTAGE - 1) ? 0 : s + 1;
    }

    // ---- epilogue: bias + store ----
    const int rrow = m0 + wm * 32 + (lane >> 2);
    const int ncol = n0 + wn * 64 + (lane & 3) * 2;

    float2 bb[8];
    #pragma unroll
    for (int nj = 0; nj < 8; nj++)
        bb[nj] = *(const float2*)&bias[ncol + nj * 8];

    #pragma unroll
    for (int m2 = 0; m2 < 2; m2++) {
        #pragma unroll
        for (int nj = 0; nj < 8; nj++) {
            const int n = ncol + nj * 8;
            size_t r0 = (size_t)(rrow + m2 * 16) * N_DIM + n;
            size_t r1 = r0 + 8 * N_DIM;
            float2 o0, o1;
            o0.x = acc[m2][nj][0] + bb[nj].x;
            o0.y = acc[m2][nj][1] + bb[nj].y;
            o1.x = acc[m2][nj][2] + bb[nj].x;
            o1.y = acc[m2][nj][3] + bb[nj].y;
            *(float2*)&out[r0] = o0;
            *(float2*)&out[r1] = o1;
        }
    }
}

// ===========================================================================
extern "C" void kernel_launch(void* const* d_in, const int* in_sizes, int n_in,
                              void* d_out, int out_size)
{
    (void)in_sizes; (void)n_in; (void)out_size;
    const float* x    = (const float*)d_in[0];
    const float* W    = (const float*)d_in[1];
    const float* bias = (const float*)d_in[2];
    const float* A    = (const float*)d_in[3];
    const float* Bm   = (const float*)d_in[4];
    float* out        = (float*)d_out;

    cudaFuncSetAttribute(gemm_mma_kernel,
                         cudaFuncAttributeMaxDynamicSharedMemorySize, SMEM_TOTAL);

    conv_x_kernel<<<dim3(NCHUNK, MT), 256>>>(x);
    conv_w_kernel<<<dim3(NCHUNK, 64), 256>>>(W, A, Bm);
    gemm_mma_kernel<<<dim3(NT, MT), 256, SMEM_TOTAL>>>(bias, out);
}

// round 5
// speedup vs baseline: 9.6664x; 1.8657x over previous
#include <cuda_runtime.h>
#include <cuda_fp16.h>
#include <cstdint>

// ---------------- problem constants ----------------
#define M_TOTAL 8192
#define K_DIM   4096
#define N_DIM   4096
#define LRANK   16

#define TM 128
#define TN 128
#define KC 64                     // fp16 elems per k-chunk (128B rows, SW128)
#define NCHUNK (K_DIM / KC)       // 64
#define MT (M_TOTAL / TM)         // 64
#define NT (N_DIM / TN)           // 32

#define A_BLK 16384               // 128x64 fp16
#define W_BLK 16384               // 128x64 fp16
#define STAGE_BYTES 32768         // A_BLK + W_BLK
#define NSTAGE 3
#define SMEM_TOTAL (NSTAGE * STAGE_BYTES)   // 98304 -> 2 CTAs/SM

// pre-converted, pre-swizzled operands (device globals = sanctioned scratch)
__device__ __align__(1024) unsigned char g_x[(size_t)MT * NCHUNK * A_BLK]; // 64MB
__device__ __align__(1024) unsigned char g_w[(size_t)NT * NCHUNK * W_BLK]; // 32MB

static __device__ __forceinline__ uint32_t smem_u32(const void* p) {
    uint32_t a;
    asm("{ .reg .u64 t; cvta.to.shared.u64 t, %1; cvt.u32.u64 %0, t; }" : "=r"(a) : "l"(p));
    return a;
}

static __device__ __forceinline__ void cp16(uint32_t dst, const void* src) {
    asm volatile("cp.async.cg.shared.global [%0], [%1], 16;" :: "r"(dst), "l"(src) : "memory");
}

#define LDSM_X4(r0, r1, r2, r3, addr)                                          \
    asm volatile("ldmatrix.sync.aligned.m8n8.x4.shared.b16 {%0,%1,%2,%3}, [%4];" \
        : "=r"(r0), "=r"(r1), "=r"(r2), "=r"(r3) : "r"(addr))

#define MMA16816(d, a0, a1, a2, a3, b0, b1)                                    \
    asm volatile("mma.sync.aligned.m16n8k16.row.col.f32.f16.f16.f32 "          \
        "{%0,%1,%2,%3}, {%4,%5,%6,%7}, {%8,%9}, {%0,%1,%2,%3};"                \
        : "+f"((d)[0]), "+f"((d)[1]), "+f"((d)[2]), "+f"((d)[3])               \
        : "r"(a0), "r"(a1), "r"(a2), "r"(a3), "r"(b0), "r"(b1))

// ===========================================================================
// conv_x: x fp32 -> fp16, SW128-swizzled 128x64 blocks
// ===========================================================================
__global__ __launch_bounds__(256)
void conv_x_kernel(const float* __restrict__ x)
{
    const int kc = blockIdx.x, mt = blockIdx.y;
    const int k0 = kc * KC, m0 = mt * TM;
    unsigned char* blk = g_x + ((size_t)(mt * NCHUNK + kc) * A_BLK);
    const int t = threadIdx.x;
    #pragma unroll
    for (int i = 0; i < (TM * KC) / 256; i++) {
        int e = t + 256 * i;
        int r = e >> 6, c = e & 63;
        float v = x[(size_t)(m0 + r) * K_DIM + k0 + c];
        uint32_t off = (uint32_t)r * 128 + (uint32_t)c * 2;
        uint32_t sw = off ^ ((off >> 3) & 0x70);
        *(__half*)(blk + sw) = __float2half_rn(v);
    }
}

// ===========================================================================
// conv_w: W' = W + B@A -> fp16, SW128-swizzled 128x64 blocks
// grid (NCHUNK, 64): each block does 64 n-rows x 64 k-cols
// ===========================================================================
__global__ __launch_bounds__(256)
void conv_w_kernel(const float* __restrict__ W, const float* __restrict__ Amat,
                   const float* __restrict__ Bmat)
{
    __shared__ float As[16][64];
    __shared__ float Bs[64][16];
    const int kc = blockIdx.x, by = blockIdx.y;
    const int k0 = kc * KC, n0 = by * 64;
    const int t = threadIdx.x;

    {   // A slab 16x64
        int r = t / 16, c4 = (t % 16) * 4;
        float4 v = *(const float4*)&Amat[(size_t)r * K_DIM + k0 + c4];
        As[r][c4+0] = v.x; As[r][c4+1] = v.y; As[r][c4+2] = v.z; As[r][c4+3] = v.w;
    }
    {   // B slab 64x16
        int nl = t / 4, r4 = (t % 4) * 4;
        float4 v = *(const float4*)&Bmat[(size_t)(n0 + nl) * LRANK + r4];
        Bs[nl][r4+0] = v.x; Bs[nl][r4+1] = v.y; Bs[nl][r4+2] = v.z; Bs[nl][r4+3] = v.w;
    }
    __syncthreads();

    const int n_tile = by >> 1;            // 128-row tiles
    const int row_base = (by & 1) * 64;
    unsigned char* blk = g_w + ((size_t)(n_tile * NCHUNK + kc) * W_BLK);

    #pragma unroll
    for (int i = 0; i < 16; i++) {
        int e = t + 256 * i;
        int rl = e >> 6, c = e & 63;
        float acc = W[(size_t)(n0 + rl) * K_DIM + k0 + c];
        #pragma unroll
        for (int r = 0; r < 16; r++) acc += Bs[rl][r] * As[r][c];
        uint32_t off = (uint32_t)(row_base + rl) * 128 + (uint32_t)c * 2;
        uint32_t sw = off ^ ((off >> 3) & 0x70);
        *(__half*)(blk + sw) = __float2half_rn(acc);
    }
}

// ===========================================================================
// GEMM: out = x @ W'^T + bias  via fp16 HMMA (mma.sync)
// CTA 128x128, 8 warps (4x2), warp tile 32x64, 3-stage cp.async pipeline
// ===========================================================================
__global__ __launch_bounds__(256, 2)
void gemm_mma_kernel(const float* __restrict__ bias, float* __restrict__ out)
{
    extern __shared__ __align__(1024) unsigned char smem[];
    const uint32_t sbase = smem_u32(smem);
    const int tid  = threadIdx.x;
    const int lane = tid & 31;
    const int wid  = tid >> 5;
    const int wm   = wid & 3;          // 4 m-groups of 32
    const int wn   = wid >> 2;         // 2 n-groups of 64
    const int nt = blockIdx.x, mt = blockIdx.y;
    const int m0 = mt * TM, n0 = nt * TN;

    const unsigned char* ga = g_x + (size_t)(mt * NCHUNK) * A_BLK;
    const unsigned char* gb = g_w + (size_t)(nt * NCHUNK) * W_BLK;

    // ---- per-thread ldmatrix addressing (SW128) ----
    const int aRow = wm * 32 + ((lane >> 3) & 1) * 8 + (lane & 7);
    const uint32_t aKsel = (lane >> 4) * 16;            // +16B for k+8 halves
    const int bRow = wn * 64 + ((lane >> 4) & 1) * 8 + (lane & 7);
    const uint32_t bKsel = ((lane >> 3) & 1) * 16;
    const uint32_t X = (uint32_t)(lane & 7) << 4;       // swizzle XOR (row&7)<<4

    float acc[2][8][4];
    #pragma unroll
    for (int i = 0; i < 2; i++)
        #pragma unroll
        for (int j = 0; j < 8; j++)
            #pragma unroll
            for (int q = 0; q < 4; q++) acc[i][j][q] = 0.f;

    // ---- async copy of one chunk into stage s ----
    auto issue = [&](int c, int s) {
        const unsigned char* srcA = ga + (size_t)c * A_BLK;
        const unsigned char* srcB = gb + (size_t)c * W_BLK;
        uint32_t st = sbase + s * STAGE_BYTES;
        #pragma unroll
        for (int i = 0; i < 4; i++) {
            uint32_t off = (uint32_t)tid * 16 + i * 4096;
            cp16(st + off, srcA + off);
        }
        #pragma unroll
        for (int i = 0; i < 4; i++) {
            uint32_t off = (uint32_t)tid * 16 + i * 4096;
            cp16(st + A_BLK + off, srcB + off);
        }
        asm volatile("cp.async.commit_group;" ::: "memory");
    };

    issue(0, 0);
    issue(1, 1);
    issue(2, 2);

    int s = 0;
    for (int c = 0; c < NCHUNK; c++) {
        asm volatile("cp.async.wait_group 2;" ::: "memory");
        __syncthreads();

        const uint32_t Ahi = sbase + s * STAGE_BYTES;
        const uint32_t Bhi = Ahi + A_BLK;

        #pragma unroll
        for (int ks = 0; ks < 4; ks++) {
            const uint32_t kb = (uint32_t)ks * 32;           // k0*2 bytes
            const uint32_t aoff = (kb + aKsel) ^ X;
            const uint32_t boff = (kb + bKsel) ^ X;

            uint32_t aH[2][4];
            #pragma unroll
            for (int m2 = 0; m2 < 2; m2++) {
                uint32_t rb = (uint32_t)(aRow + 16 * m2) * 128;
                LDSM_X4(aH[m2][0], aH[m2][1], aH[m2][2], aH[m2][3], Ahi + rb + aoff);
            }
            uint32_t bH[4][4];
            #pragma unroll
            for (int n4 = 0; n4 < 4; n4++) {
                uint32_t rb = (uint32_t)(bRow + 16 * n4) * 128;
                LDSM_X4(bH[n4][0], bH[n4][1], bH[n4][2], bH[n4][3], Bhi + rb + boff);
            }

            #pragma unroll
            for (int m2 = 0; m2 < 2; m2++) {
                #pragma unroll
                for (int nj = 0; nj < 8; nj++) {
                    const int g = nj >> 1, h = (nj & 1) * 2;
                    MMA16816(acc[m2][nj], aH[m2][0], aH[m2][1], aH[m2][2], aH[m2][3],
                             bH[g][h], bH[g][h + 1]);
                }
            }
        }

        __syncthreads();
        if (c + 3 < NCHUNK) issue(c + 3, s);
        s = (s == NSTAGE - 1) ? 0 : s + 1;
    }

    // ---- epilogue: bias + store ----
    const int rrow = m0 + wm * 32 + (lane >> 2);
    const int ncol = n0 + wn * 64 + (lane & 3) * 2;

    float2 bb[8];
    #pragma unroll
    for (int nj = 0; nj < 8; nj++)
        bb[nj] = *(const float2*)&bias[ncol + nj * 8];

    #pragma unroll
    for (int m2 = 0; m2 < 2; m2++) {
        #pragma unroll
        for (int nj = 0; nj < 8; nj++) {
            const int n = ncol + nj * 8;
            size_t r0 = (size_t)(rrow + m2 * 16) * N_DIM + n;
            size_t r1 = r0 + 8 * N_DIM;
            float2 o0, o1;
            o0.x = acc[m2][nj][0] + bb[nj].x;
            o0.y = acc[m2][nj][1] + bb[nj].y;
            o1.x = acc[m2][nj][2] + bb[nj].x;
            o1.y = acc[m2][nj][3] + bb[nj].y;
            *(float2*)&out[r0] = o0;
            *(float2*)&out[r1] = o1;
        }
    }
}

// ===========================================================================
extern "C" void kernel_launch(void* const* d_in, const int* in_sizes, int n_in,
                              void* d_out, int out_size)
{
    (void)in_sizes; (void)n_in; (void)out_size;
    const float* x    = (const float*)d_in[0];
    const float* W    = (const float*)d_in[1];
    const float* bias = (const float*)d_in[2];
    const float* A    = (const float*)d_in[3];
    const float* Bm   = (const float*)d_in[4];
    float* out        = (float*)d_out;

    cudaFuncSetAttribute(gemm_mma_kernel,
                         cudaFuncAttributeMaxDynamicSharedMemorySize, SMEM_TOTAL);

    conv_x_kernel<<<dim3(NCHUNK, MT), 256>>>(x);
    conv_w_kernel<<<dim3(NCHUNK, 64), 256>>>(W, A, Bm);
    gemm_mma_kernel<<<dim3(NT, MT), 256, SMEM_TOTAL>>>(bias, out);
}